// round 7
// baseline (speedup 1.0000x reference)
#include <cuda_runtime.h>
#include <cuda_bf16.h>
#include <math.h>
#include <stdint.h>

#define Gn   256      // graphs
#define Nn   512      // nodes per graph
#define En   16384    // edges per graph
#define Hh   256      // hidden
#define FIN  4
#define TASKS 512     // 256 home + 256 away
#define HP   128      // Hh/2 pairs

// ---------------- scratch (device globals; no allocation) ----------------
__device__ __align__(16) __nv_bfloat16 g_A[(size_t)TASKS * Nn * Hh];  // aggregate out = GEMM A
__device__ __align__(16) uint32_t      g_C[(size_t)TASKS * Nn * HP];  // GEMM out (bf16 pairs)
__device__ float g_deg[TASKS * Nn];
__device__ float g_dinv[TASKS * Nn];
__device__ float g_selfnorm[TASKS * Nn];
__device__ int   g_cnt[TASKS * Nn];
__device__ int   g_rowptr[TASKS * (Nn + 1)];
__device__ __align__(16) int2 g_edge[(size_t)TASKS * En];   // (src, f32-bits of norm)
__device__ float g_pool[TASKS * Hh];
__device__ __nv_bfloat16 g_Wtb[4 * Hh * Hh];                // bf16 weights, [l][n][k]

__device__ __forceinline__ uint32_t smem_u32(const void* p) {
    uint32_t a;
    asm("{ .reg .u64 t; cvta.to.shared.u64 t, %1; cvt.u32.u64 %0, t; }" : "=r"(a) : "l"(p));
    return a;
}
__device__ __forceinline__ void cpasync16(uint32_t dst, const void* src) {
    asm volatile("cp.async.cg.shared.global [%0], [%1], 16;" :: "r"(dst), "l"(src) : "memory");
}
__device__ __forceinline__ void ldsm_x4(uint32_t& r0, uint32_t& r1, uint32_t& r2, uint32_t& r3,
                                        uint32_t addr) {
    asm volatile("ldmatrix.sync.aligned.m8n8.x4.shared.b16 {%0,%1,%2,%3}, [%4];"
                 : "=r"(r0), "=r"(r1), "=r"(r2), "=r"(r3) : "r"(addr));
}
__device__ __forceinline__ void mma_bf16(float* c, const uint32_t* a, const uint32_t* b) {
    asm volatile(
        "mma.sync.aligned.m16n8k16.row.col.f32.bf16.bf16.f32 "
        "{%0,%1,%2,%3}, {%4,%5,%6,%7}, {%8,%9}, {%0,%1,%2,%3};"
        : "+f"(c[0]), "+f"(c[1]), "+f"(c[2]), "+f"(c[3])
        : "r"(a[0]), "r"(a[1]), "r"(a[2]), "r"(a[3]), "r"(b[0]), "r"(b[1]));
}
// exact bf16x2 -> two f32 via shift/mask (ALU pipe, no cvt)
__device__ __forceinline__ float2 bf2f2(uint32_t u) {
    float2 r;
    r.x = __uint_as_float(u << 16);
    r.y = __uint_as_float(u & 0xffff0000u);
    return r;
}

// ---------------- prep v2: smem-histogram degree / CSR build ----------------
__global__ void prep_init() {                  // zero pool only
    g_pool[blockIdx.x * 256 + threadIdx.x] = 0.0f;
}

__global__ __launch_bounds__(512) void prep_count(
        const int* __restrict__ hei, const int* __restrict__ aei,
        const float* __restrict__ hew, const float* __restrict__ aew) {
    __shared__ float sdeg[Nn];
    __shared__ int   scnt[Nn];
    int task = blockIdx.x, tid = threadIdx.x;
    sdeg[tid] = 1.0f;      // self-loop weight
    scnt[tid] = 0;
    __syncthreads();
    const int*   ei = (task < Gn) ? hei + (size_t)task * 2 * En : aei + (size_t)(task - Gn) * 2 * En;
    const float* ew = (task < Gn) ? hew + (size_t)task * En     : aew + (size_t)(task - Gn) * En;
#pragma unroll 4
    for (int it = 0; it < En / 512; it++) {
        int e = it * 512 + tid;
        int t = ei[En + e];
        float w = ew[e];
        atomicAdd(&sdeg[t], w);
        atomicAdd(&scnt[t], 1);
    }
    __syncthreads();
    g_deg[task * Nn + tid] = sdeg[tid];
    g_cnt[task * Nn + tid] = scnt[tid];
}

__global__ void prep_scan() {
    __shared__ int s[Nn];
    int task = blockIdx.x, t = threadIdx.x;
    s[t] = g_cnt[task * Nn + t];
    __syncthreads();
    for (int off = 1; off < Nn; off <<= 1) {
        int v = (t >= off) ? s[t - off] : 0;
        __syncthreads();
        s[t] += v;
        __syncthreads();
    }
    g_rowptr[task * (Nn + 1) + t + 1] = s[t];
    if (t == 0) g_rowptr[task * (Nn + 1)] = 0;
    float d  = g_deg[task * Nn + t];
    float di = rsqrtf(d);
    g_dinv[task * Nn + t] = di;
    g_selfnorm[task * Nn + t] = di * di;
}

__global__ __launch_bounds__(512) void prep_scatter(
        const int* __restrict__ hei, const int* __restrict__ aei,
        const float* __restrict__ hew, const float* __restrict__ aew) {
    __shared__ int   scnt2[Nn];
    __shared__ float sdinv[Nn];
    __shared__ int   srp[Nn];
    int task = blockIdx.x, tid = threadIdx.x;
    scnt2[tid] = 0;
    sdinv[tid] = g_dinv[task * Nn + tid];
    srp[tid]   = g_rowptr[task * (Nn + 1) + tid];
    __syncthreads();
    const int*   ei = (task < Gn) ? hei + (size_t)task * 2 * En : aei + (size_t)(task - Gn) * 2 * En;
    const float* ew = (task < Gn) ? hew + (size_t)task * En     : aew + (size_t)(task - Gn) * En;
    int2* eg = g_edge + (size_t)task * En;
#pragma unroll 4
    for (int it = 0; it < En / 512; it++) {
        int e = it * 512 + tid;
        int s = ei[e];
        int t = ei[En + e];
        float w = ew[e];
        float norm = sdinv[s] * w * sdinv[t];
        int pos = srp[t] + atomicAdd(&scnt2[t], 1);
        eg[pos] = make_int2(s, __float_as_int(norm));
    }
}

// ---------------- weight prep: Wtb[l][n][k] = bf16(Wh[l][k][n]) ----------------
__global__ void wt_prep(const float* __restrict__ Wh) {
    int l = blockIdx.y, n = blockIdx.x, k = threadIdx.x;
    g_Wtb[(size_t)l * Hh * Hh + (size_t)n * Hh + k] =
        __float2bfloat16(Wh[(size_t)l * Hh * Hh + (size_t)k * Hh + n]);
}

// ---------------- layer 0 GEMM: C = X[512,4] @ W0[4,256], bf16-pair out ----------------
__global__ void gemm0(const float* __restrict__ hx, const float* __restrict__ ax,
                      const float* __restrict__ W0) {
    int task = blockIdx.x;
    int n0 = blockIdx.y * 8;
    int h = threadIdx.x;     // pair index 0..127
    const float* x = (task < Gn) ? hx + (size_t)task * Nn * FIN
                                 : ax + (size_t)(task - Gn) * Nn * FIN;
    float wa0 = W0[2 * h],            wb0 = W0[2 * h + 1];
    float wa1 = W0[Hh + 2 * h],       wb1 = W0[Hh + 2 * h + 1];
    float wa2 = W0[2 * Hh + 2 * h],   wb2 = W0[2 * Hh + 2 * h + 1];
    float wa3 = W0[3 * Hh + 2 * h],   wb3 = W0[3 * Hh + 2 * h + 1];
    uint32_t* C = g_C + (size_t)task * Nn * HP;
#pragma unroll
    for (int i = 0; i < 8; i++) {
        int n = n0 + i;
        float4 xv = *(const float4*)(x + n * 4);
        float c0 = xv.x * wa0 + xv.y * wa1 + xv.z * wa2 + xv.w * wa3;
        float c1 = xv.x * wb0 + xv.y * wb1 + xv.z * wb2 + xv.w * wb3;
        __nv_bfloat162 p = __float22bfloat162_rn(make_float2(c0, c1));
        C[n * HP + h] = *reinterpret_cast<uint32_t*>(&p);
    }
}

// ---------------- bf16 mma.sync GEMM (unchanged, passing since r5) ----------------
#define AST 40
#define CHB (128 * AST * 2)    // 10240 B per chunk buffer

__global__ __launch_bounds__(128) void gemm_mma(int layer) {
    __shared__ __align__(128) char smg[4 * CHB];   // [A0][A1][B0][B1]

    const int task = blockIdx.z;
    const int bm = blockIdx.y * 128;
    const int bn = blockIdx.x * 128;
    const __nv_bfloat16* A = g_A + (size_t)task * Nn * Hh + (size_t)bm * Hh;
    uint32_t*            C = g_C + (size_t)task * Nn * HP + (size_t)bm * HP + bn / 2;
    const __nv_bfloat16* W = g_Wtb + (size_t)layer * Hh * Hh + (size_t)bn * Hh;

    const int tid  = threadIdx.x;
    const int lane = tid & 31;
    const int wid  = tid >> 5;
    const int m_off = (wid & 1) * 64;
    const int n_off = (wid >> 1) * 64;
    const int gid = lane >> 2;
    const int tig = lane & 3;

    const uint32_t sm0 = smem_u32(smg);

    const int a_row = (lane & 15);
    const int a_kc  = (lane >> 4) * 8;
    const int b_row = (lane & 7) + (lane >> 4) * 8;
    const int b_kc  = ((lane >> 3) & 1) * 8;

    float acc[4][8][4];
#pragma unroll
    for (int mi = 0; mi < 4; mi++)
#pragma unroll
        for (int ni = 0; ni < 8; ni++)
#pragma unroll
            for (int q = 0; q < 4; q++) acc[mi][ni][q] = 0.f;

#define ISSUE(kb)                                                               \
    {                                                                           \
        int _buf = (kb) & 1;                                                    \
        uint32_t _da = sm0 + _buf * CHB;                                        \
        uint32_t _db = sm0 + (2 + _buf) * CHB;                                  \
        _Pragma("unroll")                                                       \
        for (int it = 0; it < 4; it++) {                                        \
            int id = tid + it * 128;                                            \
            int r = id >> 2, q = id & 3;                                        \
            cpasync16(_da + r * (AST * 2) + q * 16,                             \
                      A + (size_t)r * Hh + (kb) * 32 + q * 8);                  \
        }                                                                       \
        _Pragma("unroll")                                                       \
        for (int it = 0; it < 4; it++) {                                        \
            int id = tid + it * 128;                                            \
            int r = id >> 2, q = id & 3;                                        \
            cpasync16(_db + r * (AST * 2) + q * 16,                             \
                      W + (size_t)r * Hh + (kb) * 32 + q * 8);                  \
        }                                                                       \
        asm volatile("cp.async.commit_group;" ::: "memory");                    \
    }

    ISSUE(0);
    ISSUE(1);

    for (int kb = 0; kb < 8; kb++) {
        if (kb == 7) asm volatile("cp.async.wait_group 0;" ::: "memory");
        else         asm volatile("cp.async.wait_group 1;" ::: "memory");
        __syncthreads();

        uint32_t aA = sm0 + (kb & 1) * CHB;
        uint32_t aB = sm0 + (2 + (kb & 1)) * CHB;

#pragma unroll
        for (int ks = 0; ks < 2; ks++) {
            const int k0 = ks * 16;
            uint32_t af[4][4], bf[8][2];
#pragma unroll
            for (int mi = 0; mi < 4; mi++) {
                uint32_t ad = aA + (m_off + mi * 16 + a_row) * (AST * 2) + (k0 + a_kc) * 2;
                ldsm_x4(af[mi][0], af[mi][1], af[mi][2], af[mi][3], ad);
            }
#pragma unroll
            for (int nip = 0; nip < 4; nip++) {
                uint32_t bd = aB + (n_off + nip * 16 + b_row) * (AST * 2) + (k0 + b_kc) * 2;
                ldsm_x4(bf[nip * 2][0], bf[nip * 2][1], bf[nip * 2 + 1][0], bf[nip * 2 + 1][1], bd);
            }
#pragma unroll
            for (int mi = 0; mi < 4; mi++)
#pragma unroll
                for (int ni = 0; ni < 8; ni++)
                    mma_bf16(acc[mi][ni], af[mi], bf[ni]);
        }
        __syncthreads();
        if (kb + 2 < 8) ISSUE(kb + 2);
    }

#pragma unroll
    for (int mi = 0; mi < 4; mi++) {
        int r0 = m_off + mi * 16 + gid;
#pragma unroll
        for (int ni = 0; ni < 8; ni++) {
            int pi = n_off / 2 + ni * 4 + tig;
            __nv_bfloat162 p0 = __float22bfloat162_rn(make_float2(acc[mi][ni][0], acc[mi][ni][1]));
            __nv_bfloat162 p1 = __float22bfloat162_rn(make_float2(acc[mi][ni][2], acc[mi][ni][3]));
            C[(size_t)r0 * HP + pi]       = *reinterpret_cast<uint32_t*>(&p0);
            C[(size_t)(r0 + 8) * HP + pi] = *reinterpret_cast<uint32_t*>(&p1);
        }
    }
#undef ISSUE
}

// ---------------- aggregation v3 (FIXED walker): smem-streamed edges ----------------
// grid (2, TASKS), 512 threads (16 warps; warp w owns rows [w*32, w*32+32)).
// smem: table 512x64 uint32 (128KB) + 2x 4096-edge windows (64KB) + rowptr (2KB).
#define AG_TB_B   131072
#define AG_EB_B   65536
#define AG_SMEM   (AG_TB_B + AG_EB_B + (Nn + 1) * 4 + 12)
#define WINE      4096

__global__ __launch_bounds__(512) void aggregate(const float* __restrict__ bias, int do_pool) {
    extern __shared__ __align__(16) char ag_sm[];
    uint32_t* tb  = (uint32_t*)ag_sm;                       // [512][64] bf16 pairs
    int2*     ebf = (int2*)(ag_sm + AG_TB_B);               // [2][4096]
    int*      srp = (int*)(ag_sm + AG_TB_B + AG_EB_B);      // [513]

    const int task = blockIdx.y;
    const int p0 = blockIdx.x * 64;                         // pair offset in HP
    const uint32_t* C  = g_C + (size_t)task * Nn * HP;
    const int2*     eg = g_edge + (size_t)task * En;
    const int*      rp = g_rowptr + task * (Nn + 1);
    const int tid = threadIdx.x;
    const int lane = tid & 31, w = tid >> 5;
    const uint32_t eb_addr = smem_u32(ebf);

    // stage table + rowptr (plain), edge window 0 (cp.async)
    for (int i = tid; i < Nn * 16; i += 512) {
        int n = i >> 4, q = i & 15;
        *(uint4*)&tb[n * 64 + q * 4] = *(const uint4*)(C + (size_t)n * HP + p0 + q * 4);
    }
    for (int i = tid; i < Nn + 1; i += 512) srp[i] = rp[i];
#pragma unroll
    for (int it = 0; it < 4; it++)
        cpasync16(eb_addr + it * 8192 + tid * 16, (const char*)eg + it * 8192 + tid * 16);
    asm volatile("cp.async.commit_group;" ::: "memory");
    asm volatile("cp.async.wait_group 0;" ::: "memory");
    __syncthreads();

    float4 bv = *(const float4*)(bias + p0 * 2 + lane * 4);
    float a0 = bv.x, a1 = bv.y, a2 = bv.z, a3 = bv.w;
    float q0 = 0.f, q1 = 0.f, q2 = 0.f, q3 = 0.f;

    int r = w * 32;
    const int rend = r + 32;
    int e  = srp[r];
    int re = srp[r + 1];
    uint32_t* Hout = (uint32_t*)g_A + (size_t)task * Nn * HP + p0 + 2 * lane;

    for (int win = 0; win < 4; win++) {
        if (win < 3) {
            uint32_t dst = eb_addr + ((win + 1) & 1) * 32768;
            const char* src = (const char*)(eg + (win + 1) * WINE);
#pragma unroll
            for (int it = 0; it < 4; it++)
                cpasync16(dst + it * 8192 + tid * 16, src + it * 8192 + tid * 16);
            asm volatile("cp.async.commit_group;" ::: "memory");
        }

        const int2* ew = ebf + (win & 1) * WINE - win * WINE;   // index by global e
        const int W1 = (win + 1) * WINE;

        // process this warp's rows whose edges fall inside [win*WINE, W1)
        while (r < rend && e < W1) {
            int ee = min(re, W1);   // ee >= e here (e < W1 and e <= re)
            int k = e;
            for (; k + 4 <= ee; k += 4) {
                int2 e0 = ew[k], e1 = ew[k + 1], e2 = ew[k + 2], e3 = ew[k + 3];
                uint2 u0 = *(uint2*)&tb[e0.x * 64 + 2 * lane];
                uint2 u1 = *(uint2*)&tb[e1.x * 64 + 2 * lane];
                uint2 u2 = *(uint2*)&tb[e2.x * 64 + 2 * lane];
                uint2 u3 = *(uint2*)&tb[e3.x * 64 + 2 * lane];
                float v0 = __int_as_float(e0.y), v1 = __int_as_float(e1.y);
                float v2 = __int_as_float(e2.y), v3 = __int_as_float(e3.y);
                float2 h0a = bf2f2(u0.x), h0b = bf2f2(u0.y);
                float2 h1a = bf2f2(u1.x), h1b = bf2f2(u1.y);
                float2 h2a = bf2f2(u2.x), h2b = bf2f2(u2.y);
                float2 h3a = bf2f2(u3.x), h3b = bf2f2(u3.y);
                a0 += v0 * h0a.x + v1 * h1a.x + v2 * h2a.x + v3 * h3a.x;
                a1 += v0 * h0a.y + v1 * h1a.y + v2 * h2a.y + v3 * h3a.y;
                a2 += v0 * h0b.x + v1 * h1b.x + v2 * h2b.x + v3 * h3b.x;
                a3 += v0 * h0b.y + v1 * h1b.y + v2 * h2b.y + v3 * h3b.y;
            }
            for (; k < ee; k++) {
                int2 ev = ew[k];
                uint2 u = *(uint2*)&tb[ev.x * 64 + 2 * lane];
                float v = __int_as_float(ev.y);
                float2 ha = bf2f2(u.x), hb = bf2f2(u.y);
                a0 += v * ha.x; a1 += v * ha.y; a2 += v * hb.x; a3 += v * hb.y;
            }
            e = ee;
            if (e == re) {
                // finalize row r
                float sn = g_selfnorm[task * Nn + r];
                uint2 us = *(uint2*)&tb[r * 64 + 2 * lane];
                float2 sa = bf2f2(us.x), sb = bf2f2(us.y);
                a0 += sn * sa.x; a1 += sn * sa.y; a2 += sn * sb.x; a3 += sn * sb.y;
                a0 = fmaxf(a0, 0.f); a1 = fmaxf(a1, 0.f);
                a2 = fmaxf(a2, 0.f); a3 = fmaxf(a3, 0.f);
                q0 += a0; q1 += a1; q2 += a2; q3 += a3;
                __nv_bfloat162 pA = __float22bfloat162_rn(make_float2(a0, a1));
                __nv_bfloat162 pB = __float22bfloat162_rn(make_float2(a2, a3));
                uint2 st = make_uint2(*reinterpret_cast<uint32_t*>(&pA),
                                      *reinterpret_cast<uint32_t*>(&pB));
                *(uint2*)(Hout + (size_t)r * HP) = st;
                r++;
                if (r < rend) {
                    e  = srp[r];
                    re = srp[r + 1];
                    a0 = bv.x; a1 = bv.y; a2 = bv.z; a3 = bv.w;
                }
            } else {
                break;   // row continues in next window (e == W1 < re)
            }
        }

        if (win < 3) {
            asm volatile("cp.async.wait_group 0;" ::: "memory");
            __syncthreads();
        }
    }

    if (do_pool) {
        float* pp = g_pool + task * Hh + p0 * 2 + lane * 4;
        atomicAdd(pp + 0, q0);
        atomicAdd(pp + 1, q1);
        atomicAdd(pp + 2, q2);
        atomicAdd(pp + 3, q3);
    }
}

// ---------------- FC head (pool scale folded in) ----------------
__global__ void fck(const float* __restrict__ hfeat, const float* __restrict__ afeat,
                    const float* __restrict__ fcW, const float* __restrict__ fcb,
                    float* __restrict__ out) {
    int g = blockIdx.x;
    int c = threadIdx.x >> 5;
    int lane = threadIdx.x & 31;
    const float ps = 1.0f / Nn;
    float acc = 0.f;
    for (int i = lane; i < 2 * (Hh + 6); i += 32) {
        float xv;
        if      (i < 256) xv = g_pool[g * Hh + i] * ps;
        else if (i < 262) xv = hfeat[g * 6 + (i - 256)];
        else if (i < 518) xv = g_pool[(Gn + g) * Hh + (i - 262)] * ps;
        else              xv = afeat[g * 6 + (i - 518)];
        acc += xv * fcW[i * 3 + c];
    }
#pragma unroll
    for (int o = 16; o; o >>= 1) acc += __shfl_down_sync(0xffffffff, acc, o);
    if (lane == 0) out[g * 3 + c] = acc + fcb[c];
}

// ---------------- launch ----------------
extern "C" void kernel_launch(void* const* d_in, const int* in_sizes, int n_in,
                              void* d_out, int out_size) {
    const float* home_x = (const float*)d_in[0];
    const float* away_x = (const float*)d_in[1];
    const int*   hei    = (const int*)d_in[2];
    const int*   aei    = (const int*)d_in[3];
    const float* hew    = (const float*)d_in[4];
    const float* aew    = (const float*)d_in[5];
    const float* hfeat  = (const float*)d_in[6];
    const float* afeat  = (const float*)d_in[7];
    const float* W0     = (const float*)d_in[8];
    const float* Wh     = (const float*)d_in[9];
    const float* bs     = (const float*)d_in[10];
    const float* fcW    = (const float*)d_in[11];
    const float* fcb    = (const float*)d_in[12];
    float* out = (float*)d_out;

    cudaFuncSetAttribute(aggregate, cudaFuncAttributeMaxDynamicSharedMemorySize, AG_SMEM);

    // build normalized adjacency CSR (smem histograms) + bf16 weights
    prep_init<<<TASKS * Hh / 256, 256>>>();
    prep_count<<<TASKS, 512>>>(hei, aei, hew, aew);
    prep_scan<<<TASKS, Nn>>>();
    prep_scatter<<<TASKS, 512>>>(hei, aei, hew, aew);
    wt_prep<<<dim3(Hh, 4), Hh>>>(Wh);

    // layer 0
    gemm0<<<dim3(TASKS, Nn / 8), 128>>>(home_x, away_x, W0);
    aggregate<<<dim3(2, TASKS), 512, AG_SMEM>>>(bs, 0);

    // layers 1..4 on tensor cores (mma.sync bf16)
    for (int l = 1; l < 5; l++) {
        gemm_mma<<<dim3(2, 4, TASKS), 128>>>(l - 1);
        aggregate<<<dim3(2, TASKS), 512, AG_SMEM>>>(bs + l * Hh, l == 4 ? 1 : 0);
    }

    // head
    fck<<<Gn, 96>>>(hfeat, afeat, fcW, fcb, out);
}

// round 8
// speedup vs baseline: 1.1041x; 1.1041x over previous
#include <cuda_runtime.h>
#include <cuda_bf16.h>
#include <math.h>
#include <stdint.h>

#define Gn   256      // graphs
#define Nn   512      // nodes per graph
#define En   16384    // edges per graph
#define Hh   256      // hidden
#define FIN  4
#define TASKS 512     // 256 home + 256 away
#define HP   128      // Hh/2 pairs

// ---------------- scratch (device globals; no allocation) ----------------
__device__ __align__(16) __nv_bfloat16 g_A[(size_t)TASKS * Nn * Hh];  // aggregate out = GEMM A
__device__ __align__(16) uint32_t      g_C[(size_t)TASKS * Nn * HP];  // GEMM out (bf16 pairs)
__device__ float g_deg[TASKS * Nn];
__device__ float g_dinv[TASKS * Nn];
__device__ float g_selfnorm[TASKS * Nn];
__device__ int   g_cnt[TASKS * Nn];
__device__ int   g_rowptr[TASKS * (Nn + 1)];
__device__ __align__(16) int2 g_edge[(size_t)TASKS * En];   // (src, f32-bits of norm)
__device__ float g_pool[TASKS * Hh];
__device__ __nv_bfloat16 g_Wtb[4 * Hh * Hh];                // bf16 weights, [l][n][k]

__device__ __forceinline__ uint32_t smem_u32(const void* p) {
    uint32_t a;
    asm("{ .reg .u64 t; cvta.to.shared.u64 t, %1; cvt.u32.u64 %0, t; }" : "=r"(a) : "l"(p));
    return a;
}
__device__ __forceinline__ void cpasync16(uint32_t dst, const void* src) {
    asm volatile("cp.async.cg.shared.global [%0], [%1], 16;" :: "r"(dst), "l"(src) : "memory");
}
__device__ __forceinline__ void ldsm_x4(uint32_t& r0, uint32_t& r1, uint32_t& r2, uint32_t& r3,
                                        uint32_t addr) {
    asm volatile("ldmatrix.sync.aligned.m8n8.x4.shared.b16 {%0,%1,%2,%3}, [%4];"
                 : "=r"(r0), "=r"(r1), "=r"(r2), "=r"(r3) : "r"(addr));
}
__device__ __forceinline__ void mma_bf16(float* c, const uint32_t* a, const uint32_t* b) {
    asm volatile(
        "mma.sync.aligned.m16n8k16.row.col.f32.bf16.bf16.f32 "
        "{%0,%1,%2,%3}, {%4,%5,%6,%7}, {%8,%9}, {%0,%1,%2,%3};"
        : "+f"(c[0]), "+f"(c[1]), "+f"(c[2]), "+f"(c[3])
        : "r"(a[0]), "r"(a[1]), "r"(a[2]), "r"(a[3]), "r"(b[0]), "r"(b[1]));
}
// exact bf16x2 -> two f32 via shift/mask (ALU pipe, no cvt)
__device__ __forceinline__ float2 bf2f2(uint32_t u) {
    float2 r;
    r.x = __uint_as_float(u << 16);
    r.y = __uint_as_float(u & 0xffff0000u);
    return r;
}

// ---------------- prep v2: smem-histogram degree / CSR build (kept; measured win) ----------------
__global__ void prep_init() {                  // zero pool only
    g_pool[blockIdx.x * 256 + threadIdx.x] = 0.0f;
}

__global__ __launch_bounds__(512) void prep_count(
        const int* __restrict__ hei, const int* __restrict__ aei,
        const float* __restrict__ hew, const float* __restrict__ aew) {
    __shared__ float sdeg[Nn];
    __shared__ int   scnt[Nn];
    int task = blockIdx.x, tid = threadIdx.x;
    sdeg[tid] = 1.0f;      // self-loop weight
    scnt[tid] = 0;
    __syncthreads();
    const int*   ei = (task < Gn) ? hei + (size_t)task * 2 * En : aei + (size_t)(task - Gn) * 2 * En;
    const float* ew = (task < Gn) ? hew + (size_t)task * En     : aew + (size_t)(task - Gn) * En;
#pragma unroll 4
    for (int it = 0; it < En / 512; it++) {
        int e = it * 512 + tid;
        int t = ei[En + e];
        float w = ew[e];
        atomicAdd(&sdeg[t], w);
        atomicAdd(&scnt[t], 1);
    }
    __syncthreads();
    g_deg[task * Nn + tid] = sdeg[tid];
    g_cnt[task * Nn + tid] = scnt[tid];
}

__global__ void prep_scan() {
    __shared__ int s[Nn];
    int task = blockIdx.x, t = threadIdx.x;
    s[t] = g_cnt[task * Nn + t];
    __syncthreads();
    for (int off = 1; off < Nn; off <<= 1) {
        int v = (t >= off) ? s[t - off] : 0;
        __syncthreads();
        s[t] += v;
        __syncthreads();
    }
    g_rowptr[task * (Nn + 1) + t + 1] = s[t];
    if (t == 0) g_rowptr[task * (Nn + 1)] = 0;
    float d  = g_deg[task * Nn + t];
    float di = rsqrtf(d);
    g_dinv[task * Nn + t] = di;
    g_selfnorm[task * Nn + t] = di * di;
}

__global__ __launch_bounds__(512) void prep_scatter(
        const int* __restrict__ hei, const int* __restrict__ aei,
        const float* __restrict__ hew, const float* __restrict__ aew) {
    __shared__ int   scnt2[Nn];
    __shared__ float sdinv[Nn];
    __shared__ int   srp[Nn];
    int task = blockIdx.x, tid = threadIdx.x;
    scnt2[tid] = 0;
    sdinv[tid] = g_dinv[task * Nn + tid];
    srp[tid]   = g_rowptr[task * (Nn + 1) + tid];
    __syncthreads();
    const int*   ei = (task < Gn) ? hei + (size_t)task * 2 * En : aei + (size_t)(task - Gn) * 2 * En;
    const float* ew = (task < Gn) ? hew + (size_t)task * En     : aew + (size_t)(task - Gn) * En;
    int2* eg = g_edge + (size_t)task * En;
#pragma unroll 4
    for (int it = 0; it < En / 512; it++) {
        int e = it * 512 + tid;
        int s = ei[e];
        int t = ei[En + e];
        float w = ew[e];
        float norm = sdinv[s] * w * sdinv[t];
        int pos = srp[t] + atomicAdd(&scnt2[t], 1);
        eg[pos] = make_int2(s, __float_as_int(norm));
    }
}

// ---------------- weight prep: Wtb[l][n][k] = bf16(Wh[l][k][n]) ----------------
__global__ void wt_prep(const float* __restrict__ Wh) {
    int l = blockIdx.y, n = blockIdx.x, k = threadIdx.x;
    g_Wtb[(size_t)l * Hh * Hh + (size_t)n * Hh + k] =
        __float2bfloat16(Wh[(size_t)l * Hh * Hh + (size_t)k * Hh + n]);
}

// ---------------- layer 0 GEMM: C = X[512,4] @ W0[4,256], bf16-pair out ----------------
__global__ void gemm0(const float* __restrict__ hx, const float* __restrict__ ax,
                      const float* __restrict__ W0) {
    int task = blockIdx.x;
    int n0 = blockIdx.y * 8;
    int h = threadIdx.x;     // pair index 0..127
    const float* x = (task < Gn) ? hx + (size_t)task * Nn * FIN
                                 : ax + (size_t)(task - Gn) * Nn * FIN;
    float wa0 = W0[2 * h],            wb0 = W0[2 * h + 1];
    float wa1 = W0[Hh + 2 * h],       wb1 = W0[Hh + 2 * h + 1];
    float wa2 = W0[2 * Hh + 2 * h],   wb2 = W0[2 * Hh + 2 * h + 1];
    float wa3 = W0[3 * Hh + 2 * h],   wb3 = W0[3 * Hh + 2 * h + 1];
    uint32_t* C = g_C + (size_t)task * Nn * HP;
#pragma unroll
    for (int i = 0; i < 8; i++) {
        int n = n0 + i;
        float4 xv = *(const float4*)(x + n * 4);
        float c0 = xv.x * wa0 + xv.y * wa1 + xv.z * wa2 + xv.w * wa3;
        float c1 = xv.x * wb0 + xv.y * wb1 + xv.z * wb2 + xv.w * wb3;
        __nv_bfloat162 p = __float22bfloat162_rn(make_float2(c0, c1));
        C[n * HP + h] = *reinterpret_cast<uint32_t*>(&p);
    }
}

// ---------------- bf16 mma.sync GEMM (unchanged, passing since r5) ----------------
#define AST 40
#define CHB (128 * AST * 2)    // 10240 B per chunk buffer

__global__ __launch_bounds__(128) void gemm_mma(int layer) {
    __shared__ __align__(128) char smg[4 * CHB];   // [A0][A1][B0][B1]

    const int task = blockIdx.z;
    const int bm = blockIdx.y * 128;
    const int bn = blockIdx.x * 128;
    const __nv_bfloat16* A = g_A + (size_t)task * Nn * Hh + (size_t)bm * Hh;
    uint32_t*            C = g_C + (size_t)task * Nn * HP + (size_t)bm * HP + bn / 2;
    const __nv_bfloat16* W = g_Wtb + (size_t)layer * Hh * Hh + (size_t)bn * Hh;

    const int tid  = threadIdx.x;
    const int lane = tid & 31;
    const int wid  = tid >> 5;
    const int m_off = (wid & 1) * 64;
    const int n_off = (wid >> 1) * 64;
    const int gid = lane >> 2;
    const int tig = lane & 3;

    const uint32_t sm0 = smem_u32(smg);

    const int a_row = (lane & 15);
    const int a_kc  = (lane >> 4) * 8;
    const int b_row = (lane & 7) + (lane >> 4) * 8;
    const int b_kc  = ((lane >> 3) & 1) * 8;

    float acc[4][8][4];
#pragma unroll
    for (int mi = 0; mi < 4; mi++)
#pragma unroll
        for (int ni = 0; ni < 8; ni++)
#pragma unroll
            for (int q = 0; q < 4; q++) acc[mi][ni][q] = 0.f;

#define ISSUE(kb)                                                               \
    {                                                                           \
        int _buf = (kb) & 1;                                                    \
        uint32_t _da = sm0 + _buf * CHB;                                        \
        uint32_t _db = sm0 + (2 + _buf) * CHB;                                  \
        _Pragma("unroll")                                                       \
        for (int it = 0; it < 4; it++) {                                        \
            int id = tid + it * 128;                                            \
            int r = id >> 2, q = id & 3;                                        \
            cpasync16(_da + r * (AST * 2) + q * 16,                             \
                      A + (size_t)r * Hh + (kb) * 32 + q * 8);                  \
        }                                                                       \
        _Pragma("unroll")                                                       \
        for (int it = 0; it < 4; it++) {                                        \
            int id = tid + it * 128;                                            \
            int r = id >> 2, q = id & 3;                                        \
            cpasync16(_db + r * (AST * 2) + q * 16,                             \
                      W + (size_t)r * Hh + (kb) * 32 + q * 8);                  \
        }                                                                       \
        asm volatile("cp.async.commit_group;" ::: "memory");                    \
    }

    ISSUE(0);
    ISSUE(1);

    for (int kb = 0; kb < 8; kb++) {
        if (kb == 7) asm volatile("cp.async.wait_group 0;" ::: "memory");
        else         asm volatile("cp.async.wait_group 1;" ::: "memory");
        __syncthreads();

        uint32_t aA = sm0 + (kb & 1) * CHB;
        uint32_t aB = sm0 + (2 + (kb & 1)) * CHB;

#pragma unroll
        for (int ks = 0; ks < 2; ks++) {
            const int k0 = ks * 16;
            uint32_t af[4][4], bf[8][2];
#pragma unroll
            for (int mi = 0; mi < 4; mi++) {
                uint32_t ad = aA + (m_off + mi * 16 + a_row) * (AST * 2) + (k0 + a_kc) * 2;
                ldsm_x4(af[mi][0], af[mi][1], af[mi][2], af[mi][3], ad);
            }
#pragma unroll
            for (int nip = 0; nip < 4; nip++) {
                uint32_t bd = aB + (n_off + nip * 16 + b_row) * (AST * 2) + (k0 + b_kc) * 2;
                ldsm_x4(bf[nip * 2][0], bf[nip * 2][1], bf[nip * 2 + 1][0], bf[nip * 2 + 1][1], bd);
            }
#pragma unroll
            for (int mi = 0; mi < 4; mi++)
#pragma unroll
                for (int ni = 0; ni < 8; ni++)
                    mma_bf16(acc[mi][ni], af[mi], bf[ni]);
        }
        __syncthreads();
        if (kb + 2 < 8) ISSUE(kb + 2);
    }

#pragma unroll
    for (int mi = 0; mi < 4; mi++) {
        int r0 = m_off + mi * 16 + gid;
#pragma unroll
        for (int ni = 0; ni < 8; ni++) {
            int pi = n_off / 2 + ni * 4 + tig;
            __nv_bfloat162 p0 = __float22bfloat162_rn(make_float2(acc[mi][ni][0], acc[mi][ni][1]));
            __nv_bfloat162 p1 = __float22bfloat162_rn(make_float2(acc[mi][ni][2], acc[mi][ni][3]));
            C[(size_t)r0 * HP + pi]       = *reinterpret_cast<uint32_t*>(&p0);
            C[(size_t)(r0 + 8) * HP + pi] = *reinterpret_cast<uint32_t*>(&p1);
        }
    }
#undef ISSUE
}

// ---------------- aggregation v4: r5 structure + MLP-8 edge batching ----------------
// grid (4 pair-slices, TASKS), block 256 (8 warps), 64KB dyn smem -> 3 CTAs/SM.
__global__ __launch_bounds__(256) void aggregate(const float* __restrict__ bias, int do_pool) {
    extern __shared__ uint32_t sh2[];   // [Nn][32 pairs]
    int task = blockIdx.y;
    int p0 = blockIdx.x * 32;           // pair offset
    const uint32_t* C = g_C + (size_t)task * Nn * HP;
    uint32_t* Hout = (uint32_t*)g_A + (size_t)task * Nn * HP;

    // stage [512 x 32] pair slice (pure copy, uint4)
    for (int i = threadIdx.x; i < Nn * 8; i += blockDim.x) {
        int n = i >> 3, q = i & 7;
        *(uint4*)&sh2[n * 32 + q * 4] = *(const uint4*)(C + (size_t)n * HP + p0 + q * 4);
    }
    __syncthreads();

    int lane = threadIdx.x & 31, warp = threadIdx.x >> 5;
    float b0 = bias[2 * (p0 + lane)], b1 = bias[2 * (p0 + lane) + 1];
    const int*  rp = g_rowptr + task * (Nn + 1);
    const int2* ed = g_edge + (size_t)task * En;

    float q0 = 0.f, q1 = 0.f;   // pool partials

    for (int t = warp; t < Nn; t += 8) {
        float a0 = b0, a1 = b1;
        int rs = rp[t], re = rp[t + 1];
        int e = rs;
        // MLP-8 batched blocks: 8 independent LDG.64 issued before any use
        for (; e + 8 <= re; e += 8) {
            int2 E0 = ed[e + 0], E1 = ed[e + 1], E2 = ed[e + 2], E3 = ed[e + 3];
            int2 E4 = ed[e + 4], E5 = ed[e + 5], E6 = ed[e + 6], E7 = ed[e + 7];
            uint32_t u0 = sh2[E0.x * 32 + lane], u1 = sh2[E1.x * 32 + lane];
            uint32_t u2 = sh2[E2.x * 32 + lane], u3 = sh2[E3.x * 32 + lane];
            uint32_t u4 = sh2[E4.x * 32 + lane], u5 = sh2[E5.x * 32 + lane];
            uint32_t u6 = sh2[E6.x * 32 + lane], u7 = sh2[E7.x * 32 + lane];
            float2 h0 = bf2f2(u0), h1 = bf2f2(u1), h2 = bf2f2(u2), h3 = bf2f2(u3);
            float2 h4 = bf2f2(u4), h5 = bf2f2(u5), h6 = bf2f2(u6), h7 = bf2f2(u7);
            float v0 = __int_as_float(E0.y), v1 = __int_as_float(E1.y);
            float v2 = __int_as_float(E2.y), v3 = __int_as_float(E3.y);
            float v4 = __int_as_float(E4.y), v5 = __int_as_float(E5.y);
            float v6 = __int_as_float(E6.y), v7 = __int_as_float(E7.y);
            a0 += v0 * h0.x + v1 * h1.x + v2 * h2.x + v3 * h3.x
                + v4 * h4.x + v5 * h5.x + v6 * h6.x + v7 * h7.x;
            a1 += v0 * h0.y + v1 * h1.y + v2 * h2.y + v3 * h3.y
                + v4 * h4.y + v5 * h5.y + v6 * h6.y + v7 * h7.y;
        }
        for (; e < re; e++) {
            int2 ev = ed[e];
            uint32_t u = sh2[ev.x * 32 + lane];
            float2 h = bf2f2(u);
            float v = __int_as_float(ev.y);
            a0 += v * h.x;
            a1 += v * h.y;
        }
        float sn = g_selfnorm[task * Nn + t];
        uint32_t us = sh2[t * 32 + lane];
        float2 hs = bf2f2(us);
        a0 += sn * hs.x;
        a1 += sn * hs.y;
        a0 = fmaxf(a0, 0.f); a1 = fmaxf(a1, 0.f);
        q0 += a0; q1 += a1;
        __nv_bfloat162 p = __float22bfloat162_rn(make_float2(a0, a1));
        Hout[(size_t)t * HP + p0 + lane] = *reinterpret_cast<uint32_t*>(&p);
    }

    if (do_pool) {
        atomicAdd(&g_pool[task * Hh + 2 * (p0 + lane)],     q0);
        atomicAdd(&g_pool[task * Hh + 2 * (p0 + lane) + 1], q1);
    }
}

// ---------------- FC head (pool scale folded in) ----------------
__global__ void fck(const float* __restrict__ hfeat, const float* __restrict__ afeat,
                    const float* __restrict__ fcW, const float* __restrict__ fcb,
                    float* __restrict__ out) {
    int g = blockIdx.x;
    int c = threadIdx.x >> 5;
    int lane = threadIdx.x & 31;
    const float ps = 1.0f / Nn;
    float acc = 0.f;
    for (int i = lane; i < 2 * (Hh + 6); i += 32) {
        float xv;
        if      (i < 256) xv = g_pool[g * Hh + i] * ps;
        else if (i < 262) xv = hfeat[g * 6 + (i - 256)];
        else if (i < 518) xv = g_pool[(Gn + g) * Hh + (i - 262)] * ps;
        else              xv = afeat[g * 6 + (i - 518)];
        acc += xv * fcW[i * 3 + c];
    }
#pragma unroll
    for (int o = 16; o; o >>= 1) acc += __shfl_down_sync(0xffffffff, acc, o);
    if (lane == 0) out[g * 3 + c] = acc + fcb[c];
}

// ---------------- launch ----------------
extern "C" void kernel_launch(void* const* d_in, const int* in_sizes, int n_in,
                              void* d_out, int out_size) {
    const float* home_x = (const float*)d_in[0];
    const float* away_x = (const float*)d_in[1];
    const int*   hei    = (const int*)d_in[2];
    const int*   aei    = (const int*)d_in[3];
    const float* hew    = (const float*)d_in[4];
    const float* aew    = (const float*)d_in[5];
    const float* hfeat  = (const float*)d_in[6];
    const float* afeat  = (const float*)d_in[7];
    const float* W0     = (const float*)d_in[8];
    const float* Wh     = (const float*)d_in[9];
    const float* bs     = (const float*)d_in[10];
    const float* fcW    = (const float*)d_in[11];
    const float* fcb    = (const float*)d_in[12];
    float* out = (float*)d_out;

    cudaFuncSetAttribute(aggregate, cudaFuncAttributeMaxDynamicSharedMemorySize, 65536);

    // build normalized adjacency CSR (smem histograms) + bf16 weights
    prep_init<<<TASKS * Hh / 256, 256>>>();
    prep_count<<<TASKS, 512>>>(hei, aei, hew, aew);
    prep_scan<<<TASKS, Nn>>>();
    prep_scatter<<<TASKS, 512>>>(hei, aei, hew, aew);
    wt_prep<<<dim3(Hh, 4), Hh>>>(Wh);

    // layer 0
    gemm0<<<dim3(TASKS, Nn / 8), 128>>>(home_x, away_x, W0);
    aggregate<<<dim3(4, TASKS), 256, 65536>>>(bs, 0);

    // layers 1..4 on tensor cores (mma.sync bf16)
    for (int l = 1; l < 5; l++) {
        gemm_mma<<<dim3(2, 4, TASKS), 128>>>(l - 1);
        aggregate<<<dim3(4, TASKS), 256, 65536>>>(bs + l * Hh, l == 4 ? 1 : 0);
    }

    // head
    fck<<<Gn, 96>>>(hfeat, afeat, fcW, fcb, out);
}

// round 9
// speedup vs baseline: 2.4923x; 2.2573x over previous
#include <cuda_runtime.h>
#include <cuda_bf16.h>
#include <math.h>
#include <stdint.h>

#define Gn   256      // graphs
#define Nn   512      // nodes per graph
#define En   16384    // edges per graph
#define Hh   256      // hidden
#define FIN  4
#define TASKS 512     // 256 home + 256 away
#define HP   128      // Hh/2 pairs

// ---------------- scratch (device globals; no allocation) ----------------
__device__ __align__(16) __nv_bfloat16 g_A[(size_t)TASKS * Nn * Hh];   // agg out = feature-GEMM A
__device__ __align__(16) uint32_t      g_C[(size_t)TASKS * Nn * HP];   // GEMM out (bf16 pairs) = agg B
__device__ __align__(16) __nv_bfloat16 g_Ad[(size_t)TASKS * Nn * Nn];  // dense normalized adjacency
__device__ float g_dinv[TASKS * Nn];
__device__ float g_selfnorm[TASKS * Nn];
__device__ float g_pool[TASKS * Hh];
__device__ __nv_bfloat16 g_Wtb[4 * Hh * Hh];                // bf16 weights, [l][n][k]

__device__ __forceinline__ uint32_t smem_u32(const void* p) {
    uint32_t a;
    asm("{ .reg .u64 t; cvta.to.shared.u64 t, %1; cvt.u32.u64 %0, t; }" : "=r"(a) : "l"(p));
    return a;
}
__device__ __forceinline__ void cpasync16(uint32_t dst, const void* src) {
    asm volatile("cp.async.cg.shared.global [%0], [%1], 16;" :: "r"(dst), "l"(src) : "memory");
}
__device__ __forceinline__ void ldsm_x4(uint32_t& r0, uint32_t& r1, uint32_t& r2, uint32_t& r3,
                                        uint32_t addr) {
    asm volatile("ldmatrix.sync.aligned.m8n8.x4.shared.b16 {%0,%1,%2,%3}, [%4];"
                 : "=r"(r0), "=r"(r1), "=r"(r2), "=r"(r3) : "r"(addr));
}
__device__ __forceinline__ void ldsm_x4_t(uint32_t& r0, uint32_t& r1, uint32_t& r2, uint32_t& r3,
                                          uint32_t addr) {
    asm volatile("ldmatrix.sync.aligned.m8n8.x4.trans.shared.b16 {%0,%1,%2,%3}, [%4];"
                 : "=r"(r0), "=r"(r1), "=r"(r2), "=r"(r3) : "r"(addr));
}
__device__ __forceinline__ void mma_bf16(float* c, const uint32_t* a, const uint32_t* b) {
    asm volatile(
        "mma.sync.aligned.m16n8k16.row.col.f32.bf16.bf16.f32 "
        "{%0,%1,%2,%3}, {%4,%5,%6,%7}, {%8,%9}, {%0,%1,%2,%3};"
        : "+f"(c[0]), "+f"(c[1]), "+f"(c[2]), "+f"(c[3])
        : "r"(a[0]), "r"(a[1]), "r"(a[2]), "r"(a[3]), "r"(b[0]), "r"(b[1]));
}

// ---------------- prep: degree -> dinv/selfnorm (smem histogram) ----------------
__global__ void prep_init() {                  // zero pool
    g_pool[blockIdx.x * 256 + threadIdx.x] = 0.0f;
}

__global__ __launch_bounds__(512) void prep_degree(
        const int* __restrict__ hei, const int* __restrict__ aei,
        const float* __restrict__ hew, const float* __restrict__ aew) {
    __shared__ float sdeg[Nn];
    int task = blockIdx.x, tid = threadIdx.x;
    sdeg[tid] = 1.0f;      // self-loop weight
    __syncthreads();
    const int*   ei = (task < Gn) ? hei + (size_t)task * 2 * En : aei + (size_t)(task - Gn) * 2 * En;
    const float* ew = (task < Gn) ? hew + (size_t)task * En     : aew + (size_t)(task - Gn) * En;
#pragma unroll 4
    for (int it = 0; it < En / 512; it++) {
        int e = it * 512 + tid;
        atomicAdd(&sdeg[ei[En + e]], ew[e]);
    }
    __syncthreads();
    float di = rsqrtf(sdeg[tid]);
    g_dinv[task * Nn + tid] = di;
    g_selfnorm[task * Nn + tid] = di * di;
}

// ---------------- dense adjacency build ----------------
__global__ void zero_Ad() {    // 16.8M uint4
    size_t i = (size_t)blockIdx.x * 256 + threadIdx.x;
    ((uint4*)g_Ad)[i] = make_uint4(0, 0, 0, 0);
}

__global__ __launch_bounds__(512) void build_Ad(
        const int* __restrict__ hei, const int* __restrict__ aei,
        const float* __restrict__ hew, const float* __restrict__ aew) {
    __shared__ float sdinv[Nn];
    int task = blockIdx.x, tid = threadIdx.x;
    sdinv[tid] = g_dinv[task * Nn + tid];
    __syncthreads();
    const int*   ei = (task < Gn) ? hei + (size_t)task * 2 * En : aei + (size_t)(task - Gn) * 2 * En;
    const float* ew = (task < Gn) ? hew + (size_t)task * En     : aew + (size_t)(task - Gn) * En;
    __nv_bfloat16* Ad = g_Ad + (size_t)task * Nn * Nn;
#pragma unroll 4
    for (int it = 0; it < En / 512; it++) {
        int e = it * 512 + tid;
        int s = ei[e];
        int t = ei[En + e];
        float norm = sdinv[s] * ew[e] * sdinv[t];
        atomicAdd(Ad + (size_t)t * Nn + s, __float2bfloat16(norm));
    }
    // diagonal self-loop term (atomic: self-edges may exist)
    atomicAdd(Ad + (size_t)tid * Nn + tid, __float2bfloat16(g_selfnorm[task * Nn + tid]));
}

// ---------------- weight prep: Wtb[l][n][k] = bf16(Wh[l][k][n]) ----------------
__global__ void wt_prep(const float* __restrict__ Wh) {
    int l = blockIdx.y, n = blockIdx.x, k = threadIdx.x;
    g_Wtb[(size_t)l * Hh * Hh + (size_t)n * Hh + k] =
        __float2bfloat16(Wh[(size_t)l * Hh * Hh + (size_t)k * Hh + n]);
}

// ---------------- layer 0 GEMM: C = X[512,4] @ W0[4,256], bf16-pair out ----------------
__global__ void gemm0(const float* __restrict__ hx, const float* __restrict__ ax,
                      const float* __restrict__ W0) {
    int task = blockIdx.x;
    int n0 = blockIdx.y * 8;
    int h = threadIdx.x;     // pair index 0..127
    const float* x = (task < Gn) ? hx + (size_t)task * Nn * FIN
                                 : ax + (size_t)(task - Gn) * Nn * FIN;
    float wa0 = W0[2 * h],            wb0 = W0[2 * h + 1];
    float wa1 = W0[Hh + 2 * h],       wb1 = W0[Hh + 2 * h + 1];
    float wa2 = W0[2 * Hh + 2 * h],   wb2 = W0[2 * Hh + 2 * h + 1];
    float wa3 = W0[3 * Hh + 2 * h],   wb3 = W0[3 * Hh + 2 * h + 1];
    uint32_t* C = g_C + (size_t)task * Nn * HP;
#pragma unroll
    for (int i = 0; i < 8; i++) {
        int n = n0 + i;
        float4 xv = *(const float4*)(x + n * 4);
        float c0 = xv.x * wa0 + xv.y * wa1 + xv.z * wa2 + xv.w * wa3;
        float c1 = xv.x * wb0 + xv.y * wb1 + xv.z * wb2 + xv.w * wb3;
        __nv_bfloat162 p = __float22bfloat162_rn(make_float2(c0, c1));
        C[n * HP + h] = *reinterpret_cast<uint32_t*>(&p);
    }
}

// ---------------- bf16 mma.sync feature GEMM (unchanged, passing since r5) ----------------
#define AST 40
#define CHB (128 * AST * 2)    // 10240 B per chunk buffer

__global__ __launch_bounds__(128) void gemm_mma(int layer) {
    __shared__ __align__(128) char smg[4 * CHB];   // [A0][A1][B0][B1]

    const int task = blockIdx.z;
    const int bm = blockIdx.y * 128;
    const int bn = blockIdx.x * 128;
    const __nv_bfloat16* A = g_A + (size_t)task * Nn * Hh + (size_t)bm * Hh;
    uint32_t*            C = g_C + (size_t)task * Nn * HP + (size_t)bm * HP + bn / 2;
    const __nv_bfloat16* W = g_Wtb + (size_t)layer * Hh * Hh + (size_t)bn * Hh;

    const int tid  = threadIdx.x;
    const int lane = tid & 31;
    const int wid  = tid >> 5;
    const int m_off = (wid & 1) * 64;
    const int n_off = (wid >> 1) * 64;
    const int gid = lane >> 2;
    const int tig = lane & 3;

    const uint32_t sm0 = smem_u32(smg);

    const int a_row = (lane & 15);
    const int a_kc  = (lane >> 4) * 8;
    const int b_row = (lane & 7) + (lane >> 4) * 8;
    const int b_kc  = ((lane >> 3) & 1) * 8;

    float acc[4][8][4];
#pragma unroll
    for (int mi = 0; mi < 4; mi++)
#pragma unroll
        for (int ni = 0; ni < 8; ni++)
#pragma unroll
            for (int q = 0; q < 4; q++) acc[mi][ni][q] = 0.f;

#define ISSUE(kb)                                                               \
    {                                                                           \
        int _buf = (kb) & 1;                                                    \
        uint32_t _da = sm0 + _buf * CHB;                                        \
        uint32_t _db = sm0 + (2 + _buf) * CHB;                                  \
        _Pragma("unroll")                                                       \
        for (int it = 0; it < 4; it++) {                                        \
            int id = tid + it * 128;                                            \
            int r = id >> 2, q = id & 3;                                        \
            cpasync16(_da + r * (AST * 2) + q * 16,                             \
                      A + (size_t)r * Hh + (kb) * 32 + q * 8);                  \
        }                                                                       \
        _Pragma("unroll")                                                       \
        for (int it = 0; it < 4; it++) {                                        \
            int id = tid + it * 128;                                            \
            int r = id >> 2, q = id & 3;                                        \
            cpasync16(_db + r * (AST * 2) + q * 16,                             \
                      W + (size_t)r * Hh + (kb) * 32 + q * 8);                  \
        }                                                                       \
        asm volatile("cp.async.commit_group;" ::: "memory");                    \
    }

    ISSUE(0);
    ISSUE(1);

    for (int kb = 0; kb < 8; kb++) {
        if (kb == 7) asm volatile("cp.async.wait_group 0;" ::: "memory");
        else         asm volatile("cp.async.wait_group 1;" ::: "memory");
        __syncthreads();

        uint32_t aA = sm0 + (kb & 1) * CHB;
        uint32_t aB = sm0 + (2 + (kb & 1)) * CHB;

#pragma unroll
        for (int ks = 0; ks < 2; ks++) {
            const int k0 = ks * 16;
            uint32_t af[4][4], bf[8][2];
#pragma unroll
            for (int mi = 0; mi < 4; mi++) {
                uint32_t ad = aA + (m_off + mi * 16 + a_row) * (AST * 2) + (k0 + a_kc) * 2;
                ldsm_x4(af[mi][0], af[mi][1], af[mi][2], af[mi][3], ad);
            }
#pragma unroll
            for (int nip = 0; nip < 4; nip++) {
                uint32_t bd = aB + (n_off + nip * 16 + b_row) * (AST * 2) + (k0 + b_kc) * 2;
                ldsm_x4(bf[nip * 2][0], bf[nip * 2][1], bf[nip * 2 + 1][0], bf[nip * 2 + 1][1], bd);
            }
#pragma unroll
            for (int mi = 0; mi < 4; mi++)
#pragma unroll
                for (int ni = 0; ni < 8; ni++)
                    mma_bf16(acc[mi][ni], af[mi], bf[ni]);
        }
        __syncthreads();
        if (kb + 2 < 8) ISSUE(kb + 2);
    }

#pragma unroll
    for (int mi = 0; mi < 4; mi++) {
        int r0 = m_off + mi * 16 + gid;
#pragma unroll
        for (int ni = 0; ni < 8; ni++) {
            int pi = n_off / 2 + ni * 4 + tig;
            __nv_bfloat162 p0 = __float22bfloat162_rn(make_float2(acc[mi][ni][0], acc[mi][ni][1]));
            __nv_bfloat162 p1 = __float22bfloat162_rn(make_float2(acc[mi][ni][2], acc[mi][ni][3]));
            C[(size_t)r0 * HP + pi]       = *reinterpret_cast<uint32_t*>(&p0);
            C[(size_t)(r0 + 8) * HP + pi] = *reinterpret_cast<uint32_t*>(&p1);
        }
    }
#undef ISSUE
}

// ---------------- dense aggregation GEMM: Hout = relu(Ahat[512,512] @ T[512,256] + b) ----------------
// CTA tile 128(m) x 128(n channels), K=512 (16 chunks of 32). grid (2, 4, 512).
// A chunk: [128 m][32 k] bf16, 80B padded rows (same as gemm_mma A).
// B chunk: [32 k][128 n] bf16, 256B rows, 16B-chunk XOR swizzle; ldmatrix.x4.trans.
#define BCHB 8192

__global__ __launch_bounds__(128) void agg_mma(const float* __restrict__ bias, int do_pool) {
    __shared__ __align__(128) char smg[2 * CHB + 2 * BCHB];   // A0 A1 B0 B1

    const int task = blockIdx.z;
    const int bm = blockIdx.y * 128;
    const int bn = blockIdx.x * 128;   // channel offset
    const __nv_bfloat16* A = g_Ad + (size_t)task * Nn * Nn + (size_t)bm * Nn;
    const __nv_bfloat16* T = (const __nv_bfloat16*)g_C + (size_t)task * Nn * Hh + bn;
    uint32_t* Hout = (uint32_t*)g_A + (size_t)task * Nn * HP + (size_t)bm * HP + bn / 2;

    const int tid  = threadIdx.x;
    const int lane = tid & 31;
    const int wid  = tid >> 5;
    const int m_off = (wid & 1) * 64;
    const int n_off = (wid >> 1) * 64;
    const int gid = lane >> 2;
    const int tig = lane & 3;

    const uint32_t sm0 = smem_u32(smg);
    const int a_row = (lane & 15);
    const int a_kc  = (lane >> 4) * 8;
    // B trans-ldmatrix lane addressing: rows k0+(lane&15), col block +8 for hi half
    const int bt_kr = (lane & 15);
    const int bt_nc = (lane >> 4) * 8;

    float acc[4][8][4];
#pragma unroll
    for (int mi = 0; mi < 4; mi++)
#pragma unroll
        for (int ni = 0; ni < 8; ni++)
#pragma unroll
            for (int q = 0; q < 4; q++) acc[mi][ni][q] = 0.f;

#define AISSUE(kb)                                                              \
    {                                                                           \
        int _buf = (kb) & 1;                                                    \
        uint32_t _da = sm0 + _buf * CHB;                                        \
        uint32_t _db = sm0 + 2 * CHB + _buf * BCHB;                             \
        _Pragma("unroll")                                                       \
        for (int it = 0; it < 4; it++) {                                        \
            int id = tid + it * 128;                                            \
            int r = id >> 2, q = id & 3;                                        \
            cpasync16(_da + r * (AST * 2) + q * 16,                             \
                      A + (size_t)r * Nn + (kb) * 32 + q * 8);                  \
        }                                                                       \
        _Pragma("unroll")                                                       \
        for (int it = 0; it < 4; it++) {                                        \
            int id = tid + it * 128;                                            \
            int r = id >> 4, q = id & 15;                                       \
            uint32_t col = (uint32_t)(q * 16) ^ ((r & 7) << 4);                 \
            cpasync16(_db + r * 256 + col,                                      \
                      T + (size_t)((kb) * 32 + r) * Hh + q * 8);                \
        }                                                                       \
        asm volatile("cp.async.commit_group;" ::: "memory");                    \
    }

    AISSUE(0);
    AISSUE(1);

    for (int kb = 0; kb < 16; kb++) {
        if (kb == 15) asm volatile("cp.async.wait_group 0;" ::: "memory");
        else          asm volatile("cp.async.wait_group 1;" ::: "memory");
        __syncthreads();

        uint32_t aA = sm0 + (kb & 1) * CHB;
        uint32_t aB = sm0 + 2 * CHB + (kb & 1) * BCHB;

#pragma unroll
        for (int ks = 0; ks < 2; ks++) {
            const int k0 = ks * 16;
            uint32_t af[4][4], bf[8][2];
#pragma unroll
            for (int mi = 0; mi < 4; mi++) {
                uint32_t ad = aA + (m_off + mi * 16 + a_row) * (AST * 2) + (k0 + a_kc) * 2;
                ldsm_x4(af[mi][0], af[mi][1], af[mi][2], af[mi][3], ad);
            }
#pragma unroll
            for (int nip = 0; nip < 4; nip++) {
                int krow = k0 + bt_kr;
                int ncol = n_off + nip * 16 + bt_nc;
                uint32_t bd = aB + krow * 256 + (((uint32_t)(ncol * 2)) ^ ((krow & 7) << 4));
                ldsm_x4_t(bf[nip * 2][0], bf[nip * 2][1], bf[nip * 2 + 1][0], bf[nip * 2 + 1][1], bd);
            }
#pragma unroll
            for (int mi = 0; mi < 4; mi++)
#pragma unroll
                for (int ni = 0; ni < 8; ni++)
                    mma_bf16(acc[mi][ni], af[mi], bf[ni]);
        }
        __syncthreads();
        if (kb + 2 < 16) AISSUE(kb + 2);
    }

    // epilogue: bias + relu + pack pairs + optional pool
    float pl0[8], pl1[8];
#pragma unroll
    for (int ni = 0; ni < 8; ni++) { pl0[ni] = 0.f; pl1[ni] = 0.f; }

#pragma unroll
    for (int mi = 0; mi < 4; mi++) {
        int r0 = m_off + mi * 16 + gid;
#pragma unroll
        for (int ni = 0; ni < 8; ni++) {
            int cl = n_off + ni * 8 + tig * 2;       // local channel in CTA tile
            float b0 = bias[bn + cl], b1 = bias[bn + cl + 1];
            float v0 = fmaxf(acc[mi][ni][0] + b0, 0.f);
            float v1 = fmaxf(acc[mi][ni][1] + b1, 0.f);
            float v2 = fmaxf(acc[mi][ni][2] + b0, 0.f);
            float v3 = fmaxf(acc[mi][ni][3] + b1, 0.f);
            pl0[ni] += v0 + v2;
            pl1[ni] += v1 + v3;
            int pi = n_off / 2 + ni * 4 + tig;
            __nv_bfloat162 p0 = __float22bfloat162_rn(make_float2(v0, v1));
            __nv_bfloat162 p1 = __float22bfloat162_rn(make_float2(v2, v3));
            Hout[(size_t)r0 * HP + pi]       = *reinterpret_cast<uint32_t*>(&p0);
            Hout[(size_t)(r0 + 8) * HP + pi] = *reinterpret_cast<uint32_t*>(&p1);
        }
    }

    if (do_pool) {
#pragma unroll
        for (int ni = 0; ni < 8; ni++) {
            int c = bn + n_off + ni * 8 + tig * 2;
            atomicAdd(&g_pool[task * Hh + c],     pl0[ni]);
            atomicAdd(&g_pool[task * Hh + c + 1], pl1[ni]);
        }
    }
#undef AISSUE
}

// ---------------- FC head (pool scale folded in) ----------------
__global__ void fck(const float* __restrict__ hfeat, const float* __restrict__ afeat,
                    const float* __restrict__ fcW, const float* __restrict__ fcb,
                    float* __restrict__ out) {
    int g = blockIdx.x;
    int c = threadIdx.x >> 5;
    int lane = threadIdx.x & 31;
    const float ps = 1.0f / Nn;
    float acc = 0.f;
    for (int i = lane; i < 2 * (Hh + 6); i += 32) {
        float xv;
        if      (i < 256) xv = g_pool[g * Hh + i] * ps;
        else if (i < 262) xv = hfeat[g * 6 + (i - 256)];
        else if (i < 518) xv = g_pool[(Gn + g) * Hh + (i - 262)] * ps;
        else              xv = afeat[g * 6 + (i - 518)];
        acc += xv * fcW[i * 3 + c];
    }
#pragma unroll
    for (int o = 16; o; o >>= 1) acc += __shfl_down_sync(0xffffffff, acc, o);
    if (lane == 0) out[g * 3 + c] = acc + fcb[c];
}

// ---------------- launch ----------------
extern "C" void kernel_launch(void* const* d_in, const int* in_sizes, int n_in,
                              void* d_out, int out_size) {
    const float* home_x = (const float*)d_in[0];
    const float* away_x = (const float*)d_in[1];
    const int*   hei    = (const int*)d_in[2];
    const int*   aei    = (const int*)d_in[3];
    const float* hew    = (const float*)d_in[4];
    const float* aew    = (const float*)d_in[5];
    const float* hfeat  = (const float*)d_in[6];
    const float* afeat  = (const float*)d_in[7];
    const float* W0     = (const float*)d_in[8];
    const float* Wh     = (const float*)d_in[9];
    const float* bs     = (const float*)d_in[10];
    const float* fcW    = (const float*)d_in[11];
    const float* fcb    = (const float*)d_in[12];
    float* out = (float*)d_out;

    // prep: dinv/selfnorm, zero + build dense adjacency, bf16 weights, zero pool
    prep_init<<<TASKS * Hh / 256, 256>>>();
    prep_degree<<<TASKS, 512>>>(hei, aei, hew, aew);
    zero_Ad<<<(int)((size_t)TASKS * Nn * Nn * 2 / 16 / 256), 256>>>();
    build_Ad<<<TASKS, 512>>>(hei, aei, hew, aew);
    wt_prep<<<dim3(Hh, 4), Hh>>>(Wh);

    // layer 0
    gemm0<<<dim3(TASKS, Nn / 8), 128>>>(home_x, away_x, W0);
    agg_mma<<<dim3(2, 4, TASKS), 128>>>(bs, 0);

    // layers 1..4
    for (int l = 1; l < 5; l++) {
        gemm_mma<<<dim3(2, 4, TASKS), 128>>>(l - 1);
        agg_mma<<<dim3(2, 4, TASKS), 128>>>(bs + l * Hh, l == 4 ? 1 : 0);
    }

    // head
    fck<<<Gn, 96>>>(hfeat, afeat, fcW, fcb, out);
}